// round 2
// baseline (speedup 1.0000x reference)
#include <cuda_runtime.h>
#include <cstdint>

// MaxUnpooling2D: updates [16,64,64,256] f32, mask [16,64,64,256] i32
// (flat index over (oH=128, oW=128, C=256), guaranteed inside the cell's
// own 2x2 window). Output [16,128,128,256] f32.
//
// Collision-free scatter-all: each input cell owns a disjoint 2x2 output
// window; every thread writes all 4 positions (selected -> update, rest -> 0).
// No zero-init pass, no atomics, output written exactly once.
//
// R2 changes vs R1:
//  - 2x work per thread (c4 lane and c4+32): 4 loads + 8 stores in flight,
//    each warp covers a full contiguous 1KB output segment per position.
//  - __ldcs / __stcs streaming hints: all traffic is touch-once; keep L2
//    from churning on dead lines.

static constexpr int B = 16, H = 64, W = 64, C = 256;
static constexpr int oW = 128;
static constexpr int C4 = C / 4;                  // 64 float4 per row
static constexpr int N8 = B * H * W * (C4 / 2);   // threads = 2,097,152

__device__ __forceinline__ int sel_of(int m) {
    // m = ((yy*oW)+xx)*C + ff ; dy = bit15, dx = bit8 -> sel = dy*2+dx
    return ((m >> 14) & 2) | ((m >> 8) & 1);
}

__global__ void __launch_bounds__(256)
maxunpool_kernel(const float4* __restrict__ upd,
                 const int4*  __restrict__ msk,
                 float4* __restrict__ out)
{
    int t = blockIdx.x * blockDim.x + threadIdx.x;
    if (t >= N8) return;

    // lane within row-half, then (w, h, b); all powers of two
    int c  = t & 31;            // c4 in [0,32)
    int w  = (t >> 5) & (W - 1);
    int h  = (t >> 11) & (H - 1);
    int b  = t >> 17;

    // input index (float4 units): row = t>>5, elements c and c+32
    int in4 = ((t & ~31) << 1) | c;

    float4 u0 = __ldcs(upd + in4);
    float4 u1 = __ldcs(upd + in4 + 32);
    int4   m0 = __ldcs(msk + in4);
    int4   m1 = __ldcs(msk + in4 + 32);

    int s00 = sel_of(m0.x), s01 = sel_of(m0.y), s02 = sel_of(m0.z), s03 = sel_of(m0.w);
    int s10 = sel_of(m1.x), s11 = sel_of(m1.y), s12 = sel_of(m1.z), s13 = sel_of(m1.w);

    // output base (float4 units): ((b*128 + 2h)*128 + 2w)*64 + c
    int base = ((((b << 7) + (h << 1)) << 7) | (w << 1)) * C4 + c;
    // strides (float4 units): dx -> +C4 (64), dy -> +oW*C4 (8192)

#pragma unroll
    for (int p = 0; p < 4; ++p) {
        int off = base + (p >> 1) * (oW * C4) + (p & 1) * C4;
        float4 v0, v1;
        v0.x = (s00 == p) ? u0.x : 0.0f;
        v0.y = (s01 == p) ? u0.y : 0.0f;
        v0.z = (s02 == p) ? u0.z : 0.0f;
        v0.w = (s03 == p) ? u0.w : 0.0f;
        v1.x = (s10 == p) ? u1.x : 0.0f;
        v1.y = (s11 == p) ? u1.y : 0.0f;
        v1.z = (s12 == p) ? u1.z : 0.0f;
        v1.w = (s13 == p) ? u1.w : 0.0f;
        __stcs(out + off,      v0);
        __stcs(out + off + 32, v1);
    }
}

extern "C" void kernel_launch(void* const* d_in, const int* in_sizes, int n_in,
                              void* d_out, int out_size)
{
    const float4* upd = (const float4*)d_in[0];
    const int4*   msk = (const int4*)d_in[1];
    float4*       out = (float4*)d_out;

    const int threads = 256;
    const int blocks = N8 / threads;  // 8192, exact
    maxunpool_kernel<<<blocks, threads>>>(upd, msk, out);
}